// round 13
// baseline (speedup 1.0000x reference)
#include <cuda_runtime.h>
#include <cuda_fp16.h>
#include <cstdint>
#include <math.h>

// Problem: x[4,2048,1024], W_qkv[3072,1024], W_proj[1024,1024] -> out[4,2048,1024]
#define KDIM 1024

// ---------------- device scratch (allocation-free) ----------------
__device__ __half g_Xf[8388608];
__device__ __half g_Wqf[3145728];
__device__ __half g_Wpf[1048576];
__device__ __half g_Qf[8388608];    // pre-scaled by 0.125*log2(e)  (base-2 logits)
__device__ __half g_Kf[8388608];
__device__ __half g_Vf[8388608];
__device__ __half g_Yf[8388608];

__device__ __forceinline__ uint32_t smem_u32(const void* p) {
    uint32_t a;
    asm("{ .reg .u64 t; cvta.to.shared.u64 t, %1; cvt.u32.u64 %0, t; }" : "=r"(a) : "l"(p));
    return a;
}

#define LDSM_X4(r0, r1, r2, r3, addr) \
    asm volatile("ldmatrix.sync.aligned.m8n8.x4.shared.b16 {%0,%1,%2,%3}, [%4];" \
                 : "=r"(r0), "=r"(r1), "=r"(r2), "=r"(r3) : "r"(addr))

#define LDSM_X4_T(r0, r1, r2, r3, addr) \
    asm volatile("ldmatrix.sync.aligned.m8n8.x4.trans.shared.b16 {%0,%1,%2,%3}, [%4];" \
                 : "=r"(r0), "=r"(r1), "=r"(r2), "=r"(r3) : "r"(addr))

#define MMA16816F(c, a, b) \
    asm volatile("mma.sync.aligned.m16n8k16.row.col.f32.f16.f16.f32 " \
                 "{%0,%1,%2,%3}, {%4,%5,%6,%7}, {%8,%9}, {%0,%1,%2,%3};" \
                 : "+f"((c)[0]), "+f"((c)[1]), "+f"((c)[2]), "+f"((c)[3]) \
                 : "r"((a)[0]), "r"((a)[1]), "r"((a)[2]), "r"((a)[3]), \
                   "r"((b)[0]), "r"((b)[1]))

#define CP_ASYNC16(dst, src) \
    asm volatile("cp.async.cg.shared.global [%0], [%1], 16;" :: "r"(dst), "l"(src) : "memory")
#define CP_COMMIT() asm volatile("cp.async.commit_group;" ::: "memory")
#define CP_WAIT1()  asm volatile("cp.async.wait_group 1;" ::: "memory")
#define CP_WAIT0()  asm volatile("cp.async.wait_group 0;" ::: "memory")

// ---------------------------------------------------------------------------
// merged conv16: fp32 -> fp16 for x, W_qkv, W_proj in ONE launch
// ---------------------------------------------------------------------------
#define N4_X  2097152
#define N4_WQ 786432
#define N4_WP 262144

__global__ __launch_bounds__(256) void conv16_all_kernel(const float* __restrict__ x,
                                                         const float* __restrict__ wq,
                                                         const float* __restrict__ wp)
{
    int i = blockIdx.x * blockDim.x + threadIdx.x;
    const float* src;
    __half* dst;
    int j;
    if (i < N4_X) {
        src = x; dst = g_Xf; j = i;
    } else if (i < N4_X + N4_WQ) {
        src = wq; dst = g_Wqf; j = i - N4_X;
    } else if (i < N4_X + N4_WQ + N4_WP) {
        src = wp; dst = g_Wpf; j = i - N4_X - N4_WQ;
    } else {
        return;
    }
    float4 v = ((const float4*)src)[j];
    __half2 a = __floats2half2_rn(v.x, v.y);
    __half2 b = __floats2half2_rn(v.z, v.w);
    ((uint2*)dst)[j] = make_uint2(*(uint32_t*)&a, *(uint32_t*)&b);
}

// ---------------------------------------------------------------------------
// HMMA fp16 single-pass GEMM: C = A * B^T, fp32 accumulate. (R7 schedule)
// CTA 128x128, 8 warps (2M x 4N), warp 64x32, K_tile=64, 16 iters,
// 2-stage cp.async issue-before-wait. 3 CTAs/SM (smem 3x73728=221KB fits).
// mode 0: QKV -> Qf(x 0.125*log2e), Kf, Vf;  mode 1: row-major fp32 Out
// ---------------------------------------------------------------------------
#define GTILE  (128 * 144)           // 18432 B
#define GSTAGE (2 * GTILE)           // 36864 B: A, B
#define GSM_TOTAL (2 * GSTAGE)       // 73728 B

__global__ __launch_bounds__(256, 3)
void gemm_hmma_kernel(const __half* __restrict__ A,
                      const __half* __restrict__ B,
                      float* __restrict__ Out, int mode)
{
    extern __shared__ char smem[];
    const int tid = threadIdx.x;
    const int wid = tid >> 5;
    const int l = tid & 31;
    const int m0 = blockIdx.y << 7;
    const int n0 = blockIdx.x << 7;
    const int warpM = wid >> 2;
    const int warpN = wid & 3;

    float acc[4][4][4];
#pragma unroll
    for (int i = 0; i < 4; ++i)
#pragma unroll
        for (int j = 0; j < 4; ++j)
#pragma unroll
            for (int k = 0; k < 4; ++k) acc[i][j][k] = 0.f;

    const int aRow = warpM * 64 + (l & 15);
    const uint32_t aOff = (uint32_t)(aRow * 144 + (((l >> 4) << 3) << 1));
    const int bRow = warpN * 32 + (l & 7) + ((l >> 4) << 3);
    const uint32_t bOff = (uint32_t)(bRow * 144 + ((((l >> 3) & 1) << 3) << 1));
    const uint32_t smb = smem_u32(smem);

    // stage issue: 2048 16B chunks, 8 per thread
    auto issue = [&](int stg, int k0) {
        char* st = smem + stg * GSTAGE;
#pragma unroll
        for (int t = 0; t < 8; ++t) {
            int ci = tid + (t << 8);         // 0..2047
            int mat = ci >> 10;              // 0 A, 1 B
            int pos = ci & 1023;
            int row = pos >> 3;
            int q = pos & 7;
            const __half* src = mat ? B : A;
            int grow = (mat ? n0 : m0) + row;
            uint32_t dst = smem_u32(st + mat * GTILE + row * 144 + (q << 4));
            CP_ASYNC16(dst, src + (size_t)grow * KDIM + k0 + (q << 3));
        }
        CP_COMMIT();
    };

    issue(0, 0);
    for (int iter = 0; iter < 16; ++iter) {
        if (iter < 15) {
            issue((iter + 1) & 1, (iter + 1) << 6);
            CP_WAIT1();
        } else {
            CP_WAIT0();
        }
        __syncthreads();

        const uint32_t sb = smb + (iter & 1) * GSTAGE;
        const uint32_t sA_u = sb + aOff;
        const uint32_t sB_u = sb + GTILE + bOff;

#pragma unroll
        for (int ks = 0; ks < 4; ++ks) {
            const uint32_t kb = (uint32_t)(ks << 5);
            uint32_t bf[4][2];
#pragma unroll
            for (int np = 0; np < 2; ++np) {
                uint32_t o = kb + (uint32_t)(np * 16 * 144);
                LDSM_X4(bf[2 * np][0], bf[2 * np][1], bf[2 * np + 1][0], bf[2 * np + 1][1], sB_u + o);
            }
            uint32_t af[4][4];
#pragma unroll
            for (int mt = 0; mt < 4; ++mt) {
                uint32_t o = kb + (uint32_t)(mt * 16 * 144);
                LDSM_X4(af[mt][0], af[mt][1], af[mt][2], af[mt][3], sA_u + o);
            }
#pragma unroll
            for (int mt = 0; mt < 4; ++mt)
#pragma unroll
                for (int nt = 0; nt < 4; ++nt)
                    MMA16816F(acc[mt][nt], af[mt], bf[nt]);
        }
        __syncthreads();
    }

    // epilogue
#pragma unroll
    for (int mt = 0; mt < 4; ++mt) {
#pragma unroll
        for (int nt = 0; nt < 4; ++nt) {
            int r0 = m0 + warpM * 64 + mt * 16 + (l >> 2);
            int col = n0 + warpN * 32 + nt * 8 + ((l & 3) << 1);
#pragma unroll
            for (int half = 0; half < 2; ++half) {
                int m = r0 + half * 8;
                float vx = acc[mt][nt][half * 2], vy = acc[mt][nt][half * 2 + 1];
                if (mode == 0) {
                    int which = col >> 10;
                    int c = col & 1023;
                    int h = c >> 6;
                    int d = c & 63;
                    int bb = m >> 11;
                    int t = m & 2047;
                    size_t idx = (size_t)(((bb << 4) | h) * 2048 + t) * 64 + d;
                    if (which == 0) {
                        // 0.125 * log2(e): base-2 logits for h2exp2 softmax
                        const float QS = 0.18033688f;
                        *(__half2*)&g_Qf[idx] = __floats2half2_rn(vx * QS, vy * QS);
                    } else if (which == 1) {
                        *(__half2*)&g_Kf[idx] = __floats2half2_rn(vx, vy);
                    } else {
                        *(__half2*)&g_Vf[idx] = __floats2half2_rn(vx, vy);
                    }
                } else {
                    *(float2*)&Out[(size_t)m * 1024 + col] = make_float2(vx, vy);
                }
            }
        }
    }
}

// ---------------------------------------------------------------------------
// Flash attention, fp16 HMMA, base-2 h2exp2 softmax, 2-stage cp.async.
// (exact R9/R10 structure — no stagger; phase-aligned warps get smem
// broadcast on shared K/V fragment reads). 3 CTAs/SM allowed.
// smem: Qf [0,18432); stage s at 18432 + s*18432: K[0,9216) V[9216,18432)
// ---------------------------------------------------------------------------
#define FQ_SZ 18432
#define FSTAGE 18432
#define FLASH_SMEM (FQ_SZ + 2 * FSTAGE)   // 55296

__device__ __forceinline__ void kv_issue(int tid, char* sb, int k0,
                                         const __half* Kf, const __half* Vf)
{
#pragma unroll
    for (int t = 0; t < 4; ++t) {
        int ci = tid + (t << 8);          // 0..1023
        int mat = ci >> 9;                // 0 K, 1 V
        int r = (ci & 511) >> 3;
        int q = ci & 7;
        const __half* src = mat ? Vf : Kf;
        uint32_t dst = smem_u32(sb + mat * 9216 + r * 144 + (q << 4));
        CP_ASYNC16(dst, src + (size_t)(k0 + r) * 64 + (q << 3));
    }
    CP_COMMIT();
}

__global__ __launch_bounds__(256, 3) void flash_hmma_kernel()
{
    extern __shared__ char sm[];
    const int tid = threadIdx.x;
    const int w = tid >> 5;
    const int l = tid & 31;
    const int bh = blockIdx.y;
    const int q0 = blockIdx.x << 7;

    const size_t hb = (size_t)bh * 2048 * 64;
    const __half* Qp = g_Qf + hb;
    const __half* Kp = g_Kf + hb;
    const __half* Vp = g_Vf + hb;

    // Q tile -> smem
#pragma unroll
    for (int t = 0; t < 4; ++t) {
        int ci = tid + (t << 8);
        int r = ci >> 3;
        int q = ci & 7;
        *(uint4*)(sm + r * 144 + (q << 4)) = *(const uint4*)(Qp + (size_t)(q0 + r) * 64 + (q << 3));
    }
    kv_issue(tid, sm + FQ_SZ, 0, Kp, Vp);
    __syncthreads();

    uint32_t qf[4][4];
    {
        uint32_t qb = smem_u32(sm) + (uint32_t)((w * 16 + (l & 15)) * 144 + (((l >> 4) << 3) << 1));
#pragma unroll
        for (int ks = 0; ks < 4; ++ks)
            LDSM_X4(qf[ks][0], qf[ks][1], qf[ks][2], qf[ks][3], qb + ks * 32);
    }

    float o[8][4];
#pragma unroll
    for (int nt = 0; nt < 8; ++nt)
#pragma unroll
        for (int j = 0; j < 4; ++j) o[nt][j] = 0.f;
    float m_[2] = {-INFINITY, -INFINITY};
    float l_[2] = {0.f, 0.f};

    const uint32_t kb_off = (uint32_t)((((l & 7) + ((l >> 4) << 3)) * 144) + ((((l >> 3) & 1) << 3) << 1));
    const uint32_t vb_off = (uint32_t)((((l & 7) + (((l >> 3) & 1) << 3)) * 144) + (((l >> 4) << 3) << 1));

    for (int jb = 0; jb < 32; ++jb) {
        if (jb + 1 < 32) {
            kv_issue(tid, sm + FQ_SZ + ((jb + 1) & 1) * FSTAGE, (jb + 1) << 6, Kp, Vp);
            CP_WAIT1();
        } else {
            CP_WAIT0();
        }
        __syncthreads();

        char* sb = sm + FQ_SZ + (jb & 1) * FSTAGE;
        const uint32_t kbase = smem_u32(sb) + kb_off;
        const uint32_t vbase = smem_u32(sb) + 9216 + vb_off;

        // S = Q K^T (base-2 logits; Q pre-scaled by 0.125*log2e)
        float s[8][4];
#pragma unroll
        for (int nt = 0; nt < 8; ++nt)
#pragma unroll
            for (int j = 0; j < 4; ++j) s[nt][j] = 0.f;

#pragma unroll
        for (int ks = 0; ks < 4; ++ks) {
            uint32_t kh_[8][2];
#pragma unroll
            for (int np = 0; np < 4; ++np) {
                uint32_t off = (uint32_t)(np * 16 * 144) + ks * 32;
                LDSM_X4(kh_[2 * np][0], kh_[2 * np][1], kh_[2 * np + 1][0], kh_[2 * np + 1][1], kbase + off);
            }
#pragma unroll
            for (int nt = 0; nt < 8; ++nt)
                MMA16816F(s[nt], qf[ks], kh_[nt]);
        }

        // online softmax, base-2
        float mx[2] = {-INFINITY, -INFINITY};
#pragma unroll
        for (int nt = 0; nt < 8; ++nt) {
            mx[0] = fmaxf(mx[0], fmaxf(s[nt][0], s[nt][1]));
            mx[1] = fmaxf(mx[1], fmaxf(s[nt][2], s[nt][3]));
        }
#pragma unroll
        for (int r = 0; r < 2; ++r) {
            mx[r] = fmaxf(mx[r], __shfl_xor_sync(0xffffffffu, mx[r], 1));
            mx[r] = fmaxf(mx[r], __shfl_xor_sync(0xffffffffu, mx[r], 2));
        }
        float mn[2], al[2];
#pragma unroll
        for (int r = 0; r < 2; ++r) {
            mn[r] = fmaxf(m_[r], mx[r]);
            al[r] = exp2f(m_[r] - mn[r]);
            m_[r] = mn[r];
        }

        // P = 2^(s - mn) as fp16 pairs (these ARE the PV A-fragments)
        uint32_t ph[8][2];
        float rs0 = 0.f, rs1 = 0.f;
#pragma unroll
        for (int nt = 0; nt < 8; ++nt) {
            __half2 e0 = h2exp2(__floats2half2_rn(s[nt][0] - mn[0], s[nt][1] - mn[0]));
            __half2 e1 = h2exp2(__floats2half2_rn(s[nt][2] - mn[1], s[nt][3] - mn[1]));
            ph[nt][0] = *(uint32_t*)&e0;
            ph[nt][1] = *(uint32_t*)&e1;
            float2 f0 = __half22float2(e0);
            float2 f1 = __half22float2(e1);
            rs0 += f0.x + f0.y;
            rs1 += f1.x + f1.y;
        }
        float rs[2] = {rs0, rs1};
#pragma unroll
        for (int r = 0; r < 2; ++r) {
            rs[r] += __shfl_xor_sync(0xffffffffu, rs[r], 1);
            rs[r] += __shfl_xor_sync(0xffffffffu, rs[r], 2);
            l_[r] = l_[r] * al[r] + rs[r];
        }
#pragma unroll
        for (int nt = 0; nt < 8; ++nt) {
            o[nt][0] *= al[0]; o[nt][1] *= al[0];
            o[nt][2] *= al[1]; o[nt][3] *= al[1];
        }

        // O += P V
#pragma unroll
        for (int ks = 0; ks < 4; ++ks) {
            const int ta = 2 * ks, tb = 2 * ks + 1;
            uint32_t pa[4] = {ph[ta][0], ph[ta][1], ph[tb][0], ph[tb][1]};
            uint32_t vf_[8][2];
#pragma unroll
            for (int np = 0; np < 4; ++np) {
                uint32_t off = (uint32_t)(ks * 16 * 144) + np * 32;
                LDSM_X4_T(vf_[2 * np][0], vf_[2 * np][1], vf_[2 * np + 1][0], vf_[2 * np + 1][1], vbase + off);
            }
#pragma unroll
            for (int nt = 0; nt < 8; ++nt)
                MMA16816F(o[nt], pa, vf_[nt]);
        }
        __syncthreads();
    }

    // epilogue: Y = O / l, fp16, layout [B,T,C]
    const int bb = bh >> 4;
    const int hh = bh & 15;
#pragma unroll
    for (int r = 0; r < 2; ++r) {
        int t = q0 + w * 16 + (l >> 2) + r * 8;
        float inv = 1.f / l_[r];
        size_t rowbase = (size_t)(bb * 2048 + t) * 1024 + hh * 64 + ((l & 3) << 1);
#pragma unroll
        for (int nt = 0; nt < 8; ++nt) {
            __half2 y2 = __floats2half2_rn(o[nt][2 * r] * inv, o[nt][2 * r + 1] * inv);
            *(__half2*)&g_Yf[rowbase + nt * 8] = y2;
        }
    }
}

// ---------------------------------------------------------------------------
extern "C" void kernel_launch(void* const* d_in, const int* in_sizes, int n_in,
                              void* d_out, int out_size)
{
    (void)in_sizes; (void)n_in; (void)out_size;
    const float* x = (const float*)d_in[0];
    const float* wq = (const float*)d_in[1];
    const float* wp = (const float*)d_in[2];
    float* out = (float*)d_out;

    cudaFuncSetAttribute(gemm_hmma_kernel, cudaFuncAttributeMaxDynamicSharedMemorySize, GSM_TOTAL);
    cudaFuncSetAttribute(flash_hmma_kernel, cudaFuncAttributeMaxDynamicSharedMemorySize, FLASH_SMEM);

    __half *xf, *wqf, *wpf, *yf;
    cudaGetSymbolAddress((void**)&xf, g_Xf);
    cudaGetSymbolAddress((void**)&wqf, g_Wqf);
    cudaGetSymbolAddress((void**)&wpf, g_Wpf);
    cudaGetSymbolAddress((void**)&yf, g_Yf);

    conv16_all_kernel<<<12288, 256>>>(x, wq, wp);

    gemm_hmma_kernel<<<dim3(24, 64), 256, GSM_TOTAL>>>(xf, wqf, nullptr, 0);
    flash_hmma_kernel<<<dim3(16, 64), 256, FLASH_SMEM>>>();
    gemm_hmma_kernel<<<dim3(8, 64), 256, GSM_TOTAL>>>(yf, wpf, out, 1);
}

// round 14
// speedup vs baseline: 1.3770x; 1.3770x over previous
#include <cuda_runtime.h>
#include <cuda_fp16.h>
#include <cstdint>
#include <math.h>

// Problem: x[4,2048,1024], W_qkv[3072,1024], W_proj[1024,1024] -> out[4,2048,1024]
#define KDIM 1024

// ---------------- device scratch (allocation-free) ----------------
__device__ __half g_Xf[8388608];
__device__ __half g_Wqf[3145728];
__device__ __half g_Wpf[1048576];
__device__ __half g_Qf[8388608];    // pre-scaled by 0.125*log2(e)  (base-2 logits)
__device__ __half g_Kf[8388608];
__device__ __half g_Vf[8388608];
__device__ __half g_Yf[8388608];

__device__ __forceinline__ uint32_t smem_u32(const void* p) {
    uint32_t a;
    asm("{ .reg .u64 t; cvta.to.shared.u64 t, %1; cvt.u32.u64 %0, t; }" : "=r"(a) : "l"(p));
    return a;
}

#define LDSM_X4(r0, r1, r2, r3, addr) \
    asm volatile("ldmatrix.sync.aligned.m8n8.x4.shared.b16 {%0,%1,%2,%3}, [%4];" \
                 : "=r"(r0), "=r"(r1), "=r"(r2), "=r"(r3) : "r"(addr))

#define LDSM_X4_T(r0, r1, r2, r3, addr) \
    asm volatile("ldmatrix.sync.aligned.m8n8.x4.trans.shared.b16 {%0,%1,%2,%3}, [%4];" \
                 : "=r"(r0), "=r"(r1), "=r"(r2), "=r"(r3) : "r"(addr))

#define MMA16816F(c, a, b) \
    asm volatile("mma.sync.aligned.m16n8k16.row.col.f32.f16.f16.f32 " \
                 "{%0,%1,%2,%3}, {%4,%5,%6,%7}, {%8,%9}, {%0,%1,%2,%3};" \
                 : "+f"((c)[0]), "+f"((c)[1]), "+f"((c)[2]), "+f"((c)[3]) \
                 : "r"((a)[0]), "r"((a)[1]), "r"((a)[2]), "r"((a)[3]), \
                   "r"((b)[0]), "r"((b)[1]))

#define CP_ASYNC16(dst, src) \
    asm volatile("cp.async.cg.shared.global [%0], [%1], 16;" :: "r"(dst), "l"(src) : "memory")
#define CP_COMMIT() asm volatile("cp.async.commit_group;" ::: "memory")
#define CP_WAIT1()  asm volatile("cp.async.wait_group 1;" ::: "memory")
#define CP_WAIT0()  asm volatile("cp.async.wait_group 0;" ::: "memory")

// ---------------------------------------------------------------------------
// merged conv16: fp32 -> fp16 for x, W_qkv, W_proj in ONE launch
// ---------------------------------------------------------------------------
#define N4_X  2097152
#define N4_WQ 786432
#define N4_WP 262144

__global__ __launch_bounds__(256) void conv16_all_kernel(const float* __restrict__ x,
                                                         const float* __restrict__ wq,
                                                         const float* __restrict__ wp)
{
    int i = blockIdx.x * blockDim.x + threadIdx.x;
    const float* src;
    __half* dst;
    int j;
    if (i < N4_X) {
        src = x; dst = g_Xf; j = i;
    } else if (i < N4_X + N4_WQ) {
        src = wq; dst = g_Wqf; j = i - N4_X;
    } else if (i < N4_X + N4_WQ + N4_WP) {
        src = wp; dst = g_Wpf; j = i - N4_X - N4_WQ;
    } else {
        return;
    }
    float4 v = ((const float4*)src)[j];
    __half2 a = __floats2half2_rn(v.x, v.y);
    __half2 b = __floats2half2_rn(v.z, v.w);
    ((uint2*)dst)[j] = make_uint2(*(uint32_t*)&a, *(uint32_t*)&b);
}

// ---------------------------------------------------------------------------
// HMMA fp16 single-pass GEMM: C = A * B^T, fp32 accumulate. (R9/R7 config —
// measured best 161.8us QKV). CTA 128x128, 8 warps (2M x 4N), warp 64x32,
// K_tile=64, 16 iters, 2-stage cp.async issue-before-wait, 2 CTAs/SM
// (RF-bound: 126 regs x 512 thr; do NOT raise to 3 — forces 80-reg spill).
// mode 0: QKV -> Qf(x 0.125*log2e), Kf, Vf;  mode 1: row-major fp32 Out
// ---------------------------------------------------------------------------
#define GTILE  (128 * 144)           // 18432 B
#define GSTAGE (2 * GTILE)           // 36864 B: A, B
#define GSM_TOTAL (2 * GSTAGE)       // 73728 B

__global__ __launch_bounds__(256, 2)
void gemm_hmma_kernel(const __half* __restrict__ A,
                      const __half* __restrict__ B,
                      float* __restrict__ Out, int mode)
{
    extern __shared__ char smem[];
    const int tid = threadIdx.x;
    const int wid = tid >> 5;
    const int l = tid & 31;
    const int m0 = blockIdx.y << 7;
    const int n0 = blockIdx.x << 7;
    const int warpM = wid >> 2;
    const int warpN = wid & 3;

    float acc[4][4][4];
#pragma unroll
    for (int i = 0; i < 4; ++i)
#pragma unroll
        for (int j = 0; j < 4; ++j)
#pragma unroll
            for (int k = 0; k < 4; ++k) acc[i][j][k] = 0.f;

    const int aRow = warpM * 64 + (l & 15);
    const uint32_t aOff = (uint32_t)(aRow * 144 + (((l >> 4) << 3) << 1));
    const int bRow = warpN * 32 + (l & 7) + ((l >> 4) << 3);
    const uint32_t bOff = (uint32_t)(bRow * 144 + ((((l >> 3) & 1) << 3) << 1));
    const uint32_t smb = smem_u32(smem);

    // stage issue: 2048 16B chunks, 8 per thread
    auto issue = [&](int stg, int k0) {
        char* st = smem + stg * GSTAGE;
#pragma unroll
        for (int t = 0; t < 8; ++t) {
            int ci = tid + (t << 8);         // 0..2047
            int mat = ci >> 10;              // 0 A, 1 B
            int pos = ci & 1023;
            int row = pos >> 3;
            int q = pos & 7;
            const __half* src = mat ? B : A;
            int grow = (mat ? n0 : m0) + row;
            uint32_t dst = smem_u32(st + mat * GTILE + row * 144 + (q << 4));
            CP_ASYNC16(dst, src + (size_t)grow * KDIM + k0 + (q << 3));
        }
        CP_COMMIT();
    };

    issue(0, 0);
    for (int iter = 0; iter < 16; ++iter) {
        if (iter < 15) {
            issue((iter + 1) & 1, (iter + 1) << 6);
            CP_WAIT1();
        } else {
            CP_WAIT0();
        }
        __syncthreads();

        const uint32_t sb = smb + (iter & 1) * GSTAGE;
        const uint32_t sA_u = sb + aOff;
        const uint32_t sB_u = sb + GTILE + bOff;

#pragma unroll
        for (int ks = 0; ks < 4; ++ks) {
            const uint32_t kb = (uint32_t)(ks << 5);
            uint32_t bf[4][2];
#pragma unroll
            for (int np = 0; np < 2; ++np) {
                uint32_t o = kb + (uint32_t)(np * 16 * 144);
                LDSM_X4(bf[2 * np][0], bf[2 * np][1], bf[2 * np + 1][0], bf[2 * np + 1][1], sB_u + o);
            }
            uint32_t af[4][4];
#pragma unroll
            for (int mt = 0; mt < 4; ++mt) {
                uint32_t o = kb + (uint32_t)(mt * 16 * 144);
                LDSM_X4(af[mt][0], af[mt][1], af[mt][2], af[mt][3], sA_u + o);
            }
#pragma unroll
            for (int mt = 0; mt < 4; ++mt)
#pragma unroll
                for (int nt = 0; nt < 4; ++nt)
                    MMA16816F(acc[mt][nt], af[mt], bf[nt]);
        }
        __syncthreads();
    }

    // epilogue
#pragma unroll
    for (int mt = 0; mt < 4; ++mt) {
#pragma unroll
        for (int nt = 0; nt < 4; ++nt) {
            int r0 = m0 + warpM * 64 + mt * 16 + (l >> 2);
            int col = n0 + warpN * 32 + nt * 8 + ((l & 3) << 1);
#pragma unroll
            for (int half = 0; half < 2; ++half) {
                int m = r0 + half * 8;
                float vx = acc[mt][nt][half * 2], vy = acc[mt][nt][half * 2 + 1];
                if (mode == 0) {
                    int which = col >> 10;
                    int c = col & 1023;
                    int h = c >> 6;
                    int d = c & 63;
                    int bb = m >> 11;
                    int t = m & 2047;
                    size_t idx = (size_t)(((bb << 4) | h) * 2048 + t) * 64 + d;
                    if (which == 0) {
                        // 0.125 * log2(e): base-2 logits for h2exp2 softmax
                        const float QS = 0.18033688f;
                        *(__half2*)&g_Qf[idx] = __floats2half2_rn(vx * QS, vy * QS);
                    } else if (which == 1) {
                        *(__half2*)&g_Kf[idx] = __floats2half2_rn(vx, vy);
                    } else {
                        *(__half2*)&g_Vf[idx] = __floats2half2_rn(vx, vy);
                    }
                } else {
                    *(float2*)&Out[(size_t)m * 1024 + col] = make_float2(vx, vy);
                }
            }
        }
    }
}

// ---------------------------------------------------------------------------
// Flash attention, fp16 HMMA, base-2 h2exp2 softmax, 2-stage cp.async.
// Exact R9 structure (phase-aligned warps -> smem broadcast on K/V reads).
// smem: Qf [0,18432); stage s at 18432 + s*18432: K[0,9216) V[9216,18432)
// ---------------------------------------------------------------------------
#define FQ_SZ 18432
#define FSTAGE 18432
#define FLASH_SMEM (FQ_SZ + 2 * FSTAGE)   // 55296

__device__ __forceinline__ void kv_issue(int tid, char* sb, int k0,
                                         const __half* Kf, const __half* Vf)
{
#pragma unroll
    for (int t = 0; t < 4; ++t) {
        int ci = tid + (t << 8);          // 0..1023
        int mat = ci >> 9;                // 0 K, 1 V
        int r = (ci & 511) >> 3;
        int q = ci & 7;
        const __half* src = mat ? Vf : Kf;
        uint32_t dst = smem_u32(sb + mat * 9216 + r * 144 + (q << 4));
        CP_ASYNC16(dst, src + (size_t)(k0 + r) * 64 + (q << 3));
    }
    CP_COMMIT();
}

__global__ __launch_bounds__(256, 2) void flash_hmma_kernel()
{
    extern __shared__ char sm[];
    const int tid = threadIdx.x;
    const int w = tid >> 5;
    const int l = tid & 31;
    const int bh = blockIdx.y;
    const int q0 = blockIdx.x << 7;

    const size_t hb = (size_t)bh * 2048 * 64;
    const __half* Qp = g_Qf + hb;
    const __half* Kp = g_Kf + hb;
    const __half* Vp = g_Vf + hb;

    // Q tile -> smem
#pragma unroll
    for (int t = 0; t < 4; ++t) {
        int ci = tid + (t << 8);
        int r = ci >> 3;
        int q = ci & 7;
        *(uint4*)(sm + r * 144 + (q << 4)) = *(const uint4*)(Qp + (size_t)(q0 + r) * 64 + (q << 3));
    }
    kv_issue(tid, sm + FQ_SZ, 0, Kp, Vp);
    __syncthreads();

    uint32_t qf[4][4];
    {
        uint32_t qb = smem_u32(sm) + (uint32_t)((w * 16 + (l & 15)) * 144 + (((l >> 4) << 3) << 1));
#pragma unroll
        for (int ks = 0; ks < 4; ++ks)
            LDSM_X4(qf[ks][0], qf[ks][1], qf[ks][2], qf[ks][3], qb + ks * 32);
    }

    float o[8][4];
#pragma unroll
    for (int nt = 0; nt < 8; ++nt)
#pragma unroll
        for (int j = 0; j < 4; ++j) o[nt][j] = 0.f;
    float m_[2] = {-INFINITY, -INFINITY};
    float l_[2] = {0.f, 0.f};

    const uint32_t kb_off = (uint32_t)((((l & 7) + ((l >> 4) << 3)) * 144) + ((((l >> 3) & 1) << 3) << 1));
    const uint32_t vb_off = (uint32_t)((((l & 7) + (((l >> 3) & 1) << 3)) * 144) + (((l >> 4) << 3) << 1));

    for (int jb = 0; jb < 32; ++jb) {
        if (jb + 1 < 32) {
            kv_issue(tid, sm + FQ_SZ + ((jb + 1) & 1) * FSTAGE, (jb + 1) << 6, Kp, Vp);
            CP_WAIT1();
        } else {
            CP_WAIT0();
        }
        __syncthreads();

        char* sb = sm + FQ_SZ + (jb & 1) * FSTAGE;
        const uint32_t kbase = smem_u32(sb) + kb_off;
        const uint32_t vbase = smem_u32(sb) + 9216 + vb_off;

        // S = Q K^T (base-2 logits; Q pre-scaled by 0.125*log2e)
        float s[8][4];
#pragma unroll
        for (int nt = 0; nt < 8; ++nt)
#pragma unroll
            for (int j = 0; j < 4; ++j) s[nt][j] = 0.f;

#pragma unroll
        for (int ks = 0; ks < 4; ++ks) {
            uint32_t kh_[8][2];
#pragma unroll
            for (int np = 0; np < 4; ++np) {
                uint32_t off = (uint32_t)(np * 16 * 144) + ks * 32;
                LDSM_X4(kh_[2 * np][0], kh_[2 * np][1], kh_[2 * np + 1][0], kh_[2 * np + 1][1], kbase + off);
            }
#pragma unroll
            for (int nt = 0; nt < 8; ++nt)
                MMA16816F(s[nt], qf[ks], kh_[nt]);
        }

        // online softmax, base-2
        float mx[2] = {-INFINITY, -INFINITY};
#pragma unroll
        for (int nt = 0; nt < 8; ++nt) {
            mx[0] = fmaxf(mx[0], fmaxf(s[nt][0], s[nt][1]));
            mx[1] = fmaxf(mx[1], fmaxf(s[nt][2], s[nt][3]));
        }
#pragma unroll
        for (int r = 0; r < 2; ++r) {
            mx[r] = fmaxf(mx[r], __shfl_xor_sync(0xffffffffu, mx[r], 1));
            mx[r] = fmaxf(mx[r], __shfl_xor_sync(0xffffffffu, mx[r], 2));
        }
        float mn[2], al[2];
#pragma unroll
        for (int r = 0; r < 2; ++r) {
            mn[r] = fmaxf(m_[r], mx[r]);
            al[r] = exp2f(m_[r] - mn[r]);
            m_[r] = mn[r];
        }

        // P = 2^(s - mn) as fp16 pairs (these ARE the PV A-fragments)
        uint32_t ph[8][2];
        float rs0 = 0.f, rs1 = 0.f;
#pragma unroll
        for (int nt = 0; nt < 8; ++nt) {
            __half2 e0 = h2exp2(__floats2half2_rn(s[nt][0] - mn[0], s[nt][1] - mn[0]));
            __half2 e1 = h2exp2(__floats2half2_rn(s[nt][2] - mn[1], s[nt][3] - mn[1]));
            ph[nt][0] = *(uint32_t*)&e0;
            ph[nt][1] = *(uint32_t*)&e1;
            float2 f0 = __half22float2(e0);
            float2 f1 = __half22float2(e1);
            rs0 += f0.x + f0.y;
            rs1 += f1.x + f1.y;
        }
        float rs[2] = {rs0, rs1};
#pragma unroll
        for (int r = 0; r < 2; ++r) {
            rs[r] += __shfl_xor_sync(0xffffffffu, rs[r], 1);
            rs[r] += __shfl_xor_sync(0xffffffffu, rs[r], 2);
            l_[r] = l_[r] * al[r] + rs[r];
        }
#pragma unroll
        for (int nt = 0; nt < 8; ++nt) {
            o[nt][0] *= al[0]; o[nt][1] *= al[0];
            o[nt][2] *= al[1]; o[nt][3] *= al[1];
        }

        // O += P V
#pragma unroll
        for (int ks = 0; ks < 4; ++ks) {
            const int ta = 2 * ks, tb = 2 * ks + 1;
            uint32_t pa[4] = {ph[ta][0], ph[ta][1], ph[tb][0], ph[tb][1]};
            uint32_t vf_[8][2];
#pragma unroll
            for (int np = 0; np < 4; ++np) {
                uint32_t off = (uint32_t)(ks * 16 * 144) + np * 32;
                LDSM_X4_T(vf_[2 * np][0], vf_[2 * np][1], vf_[2 * np + 1][0], vf_[2 * np + 1][1], vbase + off);
            }
#pragma unroll
            for (int nt = 0; nt < 8; ++nt)
                MMA16816F(o[nt], pa, vf_[nt]);
        }
        __syncthreads();
    }

    // epilogue: Y = O / l, fp16, layout [B,T,C]
    const int bb = bh >> 4;
    const int hh = bh & 15;
#pragma unroll
    for (int r = 0; r < 2; ++r) {
        int t = q0 + w * 16 + (l >> 2) + r * 8;
        float inv = 1.f / l_[r];
        size_t rowbase = (size_t)(bb * 2048 + t) * 1024 + hh * 64 + ((l & 3) << 1);
#pragma unroll
        for (int nt = 0; nt < 8; ++nt) {
            __half2 y2 = __floats2half2_rn(o[nt][2 * r] * inv, o[nt][2 * r + 1] * inv);
            *(__half2*)&g_Yf[rowbase + nt * 8] = y2;
        }
    }
}

// ---------------------------------------------------------------------------
extern "C" void kernel_launch(void* const* d_in, const int* in_sizes, int n_in,
                              void* d_out, int out_size)
{
    (void)in_sizes; (void)n_in; (void)out_size;
    const float* x = (const float*)d_in[0];
    const float* wq = (const float*)d_in[1];
    const float* wp = (const float*)d_in[2];
    float* out = (float*)d_out;

    cudaFuncSetAttribute(gemm_hmma_kernel, cudaFuncAttributeMaxDynamicSharedMemorySize, GSM_TOTAL);
    cudaFuncSetAttribute(flash_hmma_kernel, cudaFuncAttributeMaxDynamicSharedMemorySize, FLASH_SMEM);

    __half *xf, *wqf, *wpf, *yf;
    cudaGetSymbolAddress((void**)&xf, g_Xf);
    cudaGetSymbolAddress((void**)&wqf, g_Wqf);
    cudaGetSymbolAddress((void**)&wpf, g_Wpf);
    cudaGetSymbolAddress((void**)&yf, g_Yf);

    conv16_all_kernel<<<12288, 256>>>(x, wq, wp);

    gemm_hmma_kernel<<<dim3(24, 64), 256, GSM_TOTAL>>>(xf, wqf, nullptr, 0);
    flash_hmma_kernel<<<dim3(16, 64), 256, FLASH_SMEM>>>();
    gemm_hmma_kernel<<<dim3(8, 64), 256, GSM_TOTAL>>>(yf, wpf, out, 1);
}

// round 15
// speedup vs baseline: 1.3882x; 1.0081x over previous
#include <cuda_runtime.h>
#include <cuda_fp16.h>
#include <cstdint>
#include <math.h>

// Problem: x[4,2048,1024], W_qkv[3072,1024], W_proj[1024,1024] -> out[4,2048,1024]
#define KDIM 1024

// ---------------- device scratch (allocation-free) ----------------
__device__ __half g_Xf[8388608];
__device__ __half g_Wqf[3145728];
__device__ __half g_Wpf[1048576];
__device__ __half g_Qf[8388608];    // pre-scaled by 0.125*log2(e)  (base-2 logits)
__device__ __half g_Kf[8388608];
__device__ __half g_Vf[8388608];
__device__ __half g_Yf[8388608];

__device__ __forceinline__ uint32_t smem_u32(const void* p) {
    uint32_t a;
    asm("{ .reg .u64 t; cvta.to.shared.u64 t, %1; cvt.u32.u64 %0, t; }" : "=r"(a) : "l"(p));
    return a;
}

#define LDSM_X4(r0, r1, r2, r3, addr) \
    asm volatile("ldmatrix.sync.aligned.m8n8.x4.shared.b16 {%0,%1,%2,%3}, [%4];" \
                 : "=r"(r0), "=r"(r1), "=r"(r2), "=r"(r3) : "r"(addr))

#define LDSM_X4_T(r0, r1, r2, r3, addr) \
    asm volatile("ldmatrix.sync.aligned.m8n8.x4.trans.shared.b16 {%0,%1,%2,%3}, [%4];" \
                 : "=r"(r0), "=r"(r1), "=r"(r2), "=r"(r3) : "r"(addr))

#define MMA16816F(c, a, b) \
    asm volatile("mma.sync.aligned.m16n8k16.row.col.f32.f16.f16.f32 " \
                 "{%0,%1,%2,%3}, {%4,%5,%6,%7}, {%8,%9}, {%0,%1,%2,%3};" \
                 : "+f"((c)[0]), "+f"((c)[1]), "+f"((c)[2]), "+f"((c)[3]) \
                 : "r"((a)[0]), "r"((a)[1]), "r"((a)[2]), "r"((a)[3]), \
                   "r"((b)[0]), "r"((b)[1]))

#define CP_ASYNC16(dst, src) \
    asm volatile("cp.async.cg.shared.global [%0], [%1], 16;" :: "r"(dst), "l"(src) : "memory")
#define CP_COMMIT() asm volatile("cp.async.commit_group;" ::: "memory")
#define CP_WAIT1()  asm volatile("cp.async.wait_group 1;" ::: "memory")
#define CP_WAIT0()  asm volatile("cp.async.wait_group 0;" ::: "memory")

// ---------------------------------------------------------------------------
// merged conv16: fp32 -> fp16 for x, W_qkv, W_proj in ONE launch
// ---------------------------------------------------------------------------
#define N4_X  2097152
#define N4_WQ 786432
#define N4_WP 262144

__global__ __launch_bounds__(256) void conv16_all_kernel(const float* __restrict__ x,
                                                         const float* __restrict__ wq,
                                                         const float* __restrict__ wp)
{
    int i = blockIdx.x * blockDim.x + threadIdx.x;
    const float* src;
    __half* dst;
    int j;
    if (i < N4_X) {
        src = x; dst = g_Xf; j = i;
    } else if (i < N4_X + N4_WQ) {
        src = wq; dst = g_Wqf; j = i - N4_X;
    } else if (i < N4_X + N4_WQ + N4_WP) {
        src = wp; dst = g_Wpf; j = i - N4_X - N4_WQ;
    } else {
        return;
    }
    float4 v = ((const float4*)src)[j];
    __half2 a = __floats2half2_rn(v.x, v.y);
    __half2 b = __floats2half2_rn(v.z, v.w);
    ((uint2*)dst)[j] = make_uint2(*(uint32_t*)&a, *(uint32_t*)&b);
}

// ---------------------------------------------------------------------------
// HMMA fp16 single-pass GEMM: C = A * B^T, fp32 accumulate. (proven config —
// 161.8us QKV; DO NOT restructure: 3-stage/1-barrier variant regressed (R8),
// 3 CTAs/SM spills to 80 regs (R12).) CTA 128x128, 8 warps (2M x 4N),
// warp 64x32, K_tile=64, 16 iters, 2-stage cp.async issue-before-wait.
// mode 0: QKV -> Qf(x 0.125*log2e), Kf, Vf;  mode 1: row-major fp32 Out
// ---------------------------------------------------------------------------
#define GTILE  (128 * 144)           // 18432 B
#define GSTAGE (2 * GTILE)           // 36864 B: A, B
#define GSM_TOTAL (2 * GSTAGE)       // 73728 B

__global__ __launch_bounds__(256, 2)
void gemm_hmma_kernel(const __half* __restrict__ A,
                      const __half* __restrict__ B,
                      float* __restrict__ Out, int mode)
{
    extern __shared__ char smem[];
    const int tid = threadIdx.x;
    const int wid = tid >> 5;
    const int l = tid & 31;
    const int m0 = blockIdx.y << 7;
    const int n0 = blockIdx.x << 7;
    const int warpM = wid >> 2;
    const int warpN = wid & 3;

    float acc[4][4][4];
#pragma unroll
    for (int i = 0; i < 4; ++i)
#pragma unroll
        for (int j = 0; j < 4; ++j)
#pragma unroll
            for (int k = 0; k < 4; ++k) acc[i][j][k] = 0.f;

    const int aRow = warpM * 64 + (l & 15);
    const uint32_t aOff = (uint32_t)(aRow * 144 + (((l >> 4) << 3) << 1));
    const int bRow = warpN * 32 + (l & 7) + ((l >> 4) << 3);
    const uint32_t bOff = (uint32_t)(bRow * 144 + ((((l >> 3) & 1) << 3) << 1));
    const uint32_t smb = smem_u32(smem);

    // stage issue: 2048 16B chunks, 8 per thread
    auto issue = [&](int stg, int k0) {
        char* st = smem + stg * GSTAGE;
#pragma unroll
        for (int t = 0; t < 8; ++t) {
            int ci = tid + (t << 8);         // 0..2047
            int mat = ci >> 10;              // 0 A, 1 B
            int pos = ci & 1023;
            int row = pos >> 3;
            int q = pos & 7;
            const __half* src = mat ? B : A;
            int grow = (mat ? n0 : m0) + row;
            uint32_t dst = smem_u32(st + mat * GTILE + row * 144 + (q << 4));
            CP_ASYNC16(dst, src + (size_t)grow * KDIM + k0 + (q << 3));
        }
        CP_COMMIT();
    };

    issue(0, 0);
    for (int iter = 0; iter < 16; ++iter) {
        if (iter < 15) {
            issue((iter + 1) & 1, (iter + 1) << 6);
            CP_WAIT1();
        } else {
            CP_WAIT0();
        }
        __syncthreads();

        const uint32_t sb = smb + (iter & 1) * GSTAGE;
        const uint32_t sA_u = sb + aOff;
        const uint32_t sB_u = sb + GTILE + bOff;

#pragma unroll
        for (int ks = 0; ks < 4; ++ks) {
            const uint32_t kb = (uint32_t)(ks << 5);
            uint32_t bf[4][2];
#pragma unroll
            for (int np = 0; np < 2; ++np) {
                uint32_t o = kb + (uint32_t)(np * 16 * 144);
                LDSM_X4(bf[2 * np][0], bf[2 * np][1], bf[2 * np + 1][0], bf[2 * np + 1][1], sB_u + o);
            }
            uint32_t af[4][4];
#pragma unroll
            for (int mt = 0; mt < 4; ++mt) {
                uint32_t o = kb + (uint32_t)(mt * 16 * 144);
                LDSM_X4(af[mt][0], af[mt][1], af[mt][2], af[mt][3], sA_u + o);
            }
#pragma unroll
            for (int mt = 0; mt < 4; ++mt)
#pragma unroll
                for (int nt = 0; nt < 4; ++nt)
                    MMA16816F(acc[mt][nt], af[mt], bf[nt]);
        }
        __syncthreads();
    }

    // epilogue
#pragma unroll
    for (int mt = 0; mt < 4; ++mt) {
#pragma unroll
        for (int nt = 0; nt < 4; ++nt) {
            int r0 = m0 + warpM * 64 + mt * 16 + (l >> 2);
            int col = n0 + warpN * 32 + nt * 8 + ((l & 3) << 1);
#pragma unroll
            for (int half = 0; half < 2; ++half) {
                int m = r0 + half * 8;
                float vx = acc[mt][nt][half * 2], vy = acc[mt][nt][half * 2 + 1];
                if (mode == 0) {
                    int which = col >> 10;
                    int c = col & 1023;
                    int h = c >> 6;
                    int d = c & 63;
                    int bb = m >> 11;
                    int t = m & 2047;
                    size_t idx = (size_t)(((bb << 4) | h) * 2048 + t) * 64 + d;
                    if (which == 0) {
                        // 0.125 * log2(e): base-2 logits for h2exp2 softmax
                        const float QS = 0.18033688f;
                        *(__half2*)&g_Qf[idx] = __floats2half2_rn(vx * QS, vy * QS);
                    } else if (which == 1) {
                        *(__half2*)&g_Kf[idx] = __floats2half2_rn(vx, vy);
                    } else {
                        *(__half2*)&g_Vf[idx] = __floats2half2_rn(vx, vy);
                    }
                } else {
                    *(float2*)&Out[(size_t)m * 1024 + col] = make_float2(vx, vy);
                }
            }
        }
    }
}

// ---------------------------------------------------------------------------
// Flash attention, fp16 HMMA, base-2 h2exp2 softmax.
// 4-stage KV ring, TWO tiles processed per wait+barrier:
//   CP_WAIT0 -> __syncthreads -> issue tiles 2i+2,2i+3 -> process 2i, 2i+1.
// Ordering: barrier after all threads' waits makes cross-thread cp.async data
// visible; slots being overwritten were last read in iter i-1 (fenced by the
// same barrier). Halves barrier/wait count; ~2 tiles of prefetch depth.
// smem: Qf [0,18432); stage s at 18432 + s*18432 (s=0..3): K[0,9216) V[9216,)
// ---------------------------------------------------------------------------
#define FQ_SZ 18432
#define FSTAGE 18432
#define FLASH_SMEM (FQ_SZ + 4 * FSTAGE)   // 92160 (x2 CTAs = 184320 fits)

__device__ __forceinline__ void kv_issue(int tid, char* sb, int k0,
                                         const __half* Kf, const __half* Vf)
{
#pragma unroll
    for (int t = 0; t < 4; ++t) {
        int ci = tid + (t << 8);          // 0..1023
        int mat = ci >> 9;                // 0 K, 1 V
        int r = (ci & 511) >> 3;
        int q = ci & 7;
        const __half* src = mat ? Vf : Kf;
        uint32_t dst = smem_u32(sb + mat * 9216 + r * 144 + (q << 4));
        CP_ASYNC16(dst, src + (size_t)(k0 + r) * 64 + (q << 3));
    }
    CP_COMMIT();
}

__global__ __launch_bounds__(256, 2) void flash_hmma_kernel()
{
    extern __shared__ char sm[];
    const int tid = threadIdx.x;
    const int w = tid >> 5;
    const int l = tid & 31;
    const int bh = blockIdx.y;
    const int q0 = blockIdx.x << 7;

    const size_t hb = (size_t)bh * 2048 * 64;
    const __half* Qp = g_Qf + hb;
    const __half* Kp = g_Kf + hb;
    const __half* Vp = g_Vf + hb;

    // Q tile -> smem
#pragma unroll
    for (int t = 0; t < 4; ++t) {
        int ci = tid + (t << 8);
        int r = ci >> 3;
        int q = ci & 7;
        *(uint4*)(sm + r * 144 + (q << 4)) = *(const uint4*)(Qp + (size_t)(q0 + r) * 64 + (q << 3));
    }
    // prologue: tiles 0 and 1 into slots 0,1
    kv_issue(tid, sm + FQ_SZ + 0 * FSTAGE, 0, Kp, Vp);
    kv_issue(tid, sm + FQ_SZ + 1 * FSTAGE, 64, Kp, Vp);
    __syncthreads();    // Q stores visible for LDSM below

    uint32_t qf[4][4];
    {
        uint32_t qb = smem_u32(sm) + (uint32_t)((w * 16 + (l & 15)) * 144 + (((l >> 4) << 3) << 1));
#pragma unroll
        for (int ks = 0; ks < 4; ++ks)
            LDSM_X4(qf[ks][0], qf[ks][1], qf[ks][2], qf[ks][3], qb + ks * 32);
    }

    float o[8][4];
#pragma unroll
    for (int nt = 0; nt < 8; ++nt)
#pragma unroll
        for (int j = 0; j < 4; ++j) o[nt][j] = 0.f;
    float m_[2] = {-INFINITY, -INFINITY};
    float l_[2] = {0.f, 0.f};

    const uint32_t kb_off = (uint32_t)((((l & 7) + ((l >> 4) << 3)) * 144) + ((((l >> 3) & 1) << 3) << 1));
    const uint32_t vb_off = (uint32_t)((((l & 7) + (((l >> 3) & 1) << 3)) * 144) + (((l >> 4) << 3) << 1));

    for (int i2 = 0; i2 < 16; ++i2) {
        CP_WAIT0();          // tiles 2*i2, 2*i2+1 landed (nothing else in flight)
        __syncthreads();     // cross-thread visibility + fences prior reads of reused slots
        if (i2 < 15) {
            kv_issue(tid, sm + FQ_SZ + ((2 * i2 + 2) & 3) * FSTAGE, (2 * i2 + 2) << 6, Kp, Vp);
            kv_issue(tid, sm + FQ_SZ + ((2 * i2 + 3) & 3) * FSTAGE, (2 * i2 + 3) << 6, Kp, Vp);
        }

#pragma unroll
        for (int half = 0; half < 2; ++half) {
            const int jb = 2 * i2 + half;
            char* sb = sm + FQ_SZ + (jb & 3) * FSTAGE;
            const uint32_t kbase = smem_u32(sb) + kb_off;
            const uint32_t vbase = smem_u32(sb) + 9216 + vb_off;

            // S = Q K^T (base-2 logits; Q pre-scaled by 0.125*log2e)
            float s[8][4];
#pragma unroll
            for (int nt = 0; nt < 8; ++nt)
#pragma unroll
                for (int j = 0; j < 4; ++j) s[nt][j] = 0.f;

#pragma unroll
            for (int ks = 0; ks < 4; ++ks) {
                uint32_t kh_[8][2];
#pragma unroll
                for (int np = 0; np < 4; ++np) {
                    uint32_t off = (uint32_t)(np * 16 * 144) + ks * 32;
                    LDSM_X4(kh_[2 * np][0], kh_[2 * np][1], kh_[2 * np + 1][0], kh_[2 * np + 1][1], kbase + off);
                }
#pragma unroll
                for (int nt = 0; nt < 8; ++nt)
                    MMA16816F(s[nt], qf[ks], kh_[nt]);
            }

            // online softmax, base-2
            float mx[2] = {-INFINITY, -INFINITY};
#pragma unroll
            for (int nt = 0; nt < 8; ++nt) {
                mx[0] = fmaxf(mx[0], fmaxf(s[nt][0], s[nt][1]));
                mx[1] = fmaxf(mx[1], fmaxf(s[nt][2], s[nt][3]));
            }
#pragma unroll
            for (int r = 0; r < 2; ++r) {
                mx[r] = fmaxf(mx[r], __shfl_xor_sync(0xffffffffu, mx[r], 1));
                mx[r] = fmaxf(mx[r], __shfl_xor_sync(0xffffffffu, mx[r], 2));
            }
            float mn[2], al[2];
#pragma unroll
            for (int r = 0; r < 2; ++r) {
                mn[r] = fmaxf(m_[r], mx[r]);
                al[r] = exp2f(m_[r] - mn[r]);
                m_[r] = mn[r];
            }

            // P = 2^(s - mn) as fp16 pairs (these ARE the PV A-fragments)
            uint32_t ph[8][2];
            float rs0 = 0.f, rs1 = 0.f;
#pragma unroll
            for (int nt = 0; nt < 8; ++nt) {
                __half2 e0 = h2exp2(__floats2half2_rn(s[nt][0] - mn[0], s[nt][1] - mn[0]));
                __half2 e1 = h2exp2(__floats2half2_rn(s[nt][2] - mn[1], s[nt][3] - mn[1]));
                ph[nt][0] = *(uint32_t*)&e0;
                ph[nt][1] = *(uint32_t*)&e1;
                float2 f0 = __half22float2(e0);
                float2 f1 = __half22float2(e1);
                rs0 += f0.x + f0.y;
                rs1 += f1.x + f1.y;
            }
            float rs[2] = {rs0, rs1};
#pragma unroll
            for (int r = 0; r < 2; ++r) {
                rs[r] += __shfl_xor_sync(0xffffffffu, rs[r], 1);
                rs[r] += __shfl_xor_sync(0xffffffffu, rs[r], 2);
                l_[r] = l_[r] * al[r] + rs[r];
            }
#pragma unroll
            for (int nt = 0; nt < 8; ++nt) {
                o[nt][0] *= al[0]; o[nt][1] *= al[0];
                o[nt][2] *= al[1]; o[nt][3] *= al[1];
            }

            // O += P V
#pragma unroll
            for (int ks = 0; ks < 4; ++ks) {
                const int ta = 2 * ks, tb = 2 * ks + 1;
                uint32_t pa[4] = {ph[ta][0], ph[ta][1], ph[tb][0], ph[tb][1]};
                uint32_t vf_[8][2];
#pragma unroll
                for (int np = 0; np < 4; ++np) {
                    uint32_t off = (uint32_t)(ks * 16 * 144) + np * 32;
                    LDSM_X4_T(vf_[2 * np][0], vf_[2 * np][1], vf_[2 * np + 1][0], vf_[2 * np + 1][1], vbase + off);
                }
#pragma unroll
                for (int nt = 0; nt < 8; ++nt)
                    MMA16816F(o[nt], pa, vf_[nt]);
            }
        }
    }

    // epilogue: Y = O / l, fp16, layout [B,T,C]
    const int bb = bh >> 4;
    const int hh = bh & 15;
#pragma unroll
    for (int r = 0; r < 2; ++r) {
        int t = q0 + w * 16 + (l >> 2) + r * 8;
        float inv = 1.f / l_[r];
        size_t rowbase = (size_t)(bb * 2048 + t) * 1024 + hh * 64 + ((l & 3) << 1);
#pragma unroll
        for (int nt = 0; nt < 8; ++nt) {
            __half2 y2 = __floats2half2_rn(o[nt][2 * r] * inv, o[nt][2 * r + 1] * inv);
            *(__half2*)&g_Yf[rowbase + nt * 8] = y2;
        }
    }
}

// ---------------------------------------------------------------------------
extern "C" void kernel_launch(void* const* d_in, const int* in_sizes, int n_in,
                              void* d_out, int out_size)
{
    (void)in_sizes; (void)n_in; (void)out_size;
    const float* x = (const float*)d_in[0];
    const float* wq = (const float*)d_in[1];
    const float* wp = (const float*)d_in[2];
    float* out = (float*)d_out;

    cudaFuncSetAttribute(gemm_hmma_kernel, cudaFuncAttributeMaxDynamicSharedMemorySize, GSM_TOTAL);
    cudaFuncSetAttribute(flash_hmma_kernel, cudaFuncAttributeMaxDynamicSharedMemorySize, FLASH_SMEM);

    __half *xf, *wqf, *wpf, *yf;
    cudaGetSymbolAddress((void**)&xf, g_Xf);
    cudaGetSymbolAddress((void**)&wqf, g_Wqf);
    cudaGetSymbolAddress((void**)&wpf, g_Wpf);
    cudaGetSymbolAddress((void**)&yf, g_Yf);

    conv16_all_kernel<<<12288, 256>>>(x, wq, wp);

    gemm_hmma_kernel<<<dim3(24, 64), 256, GSM_TOTAL>>>(xf, wqf, nullptr, 0);
    flash_hmma_kernel<<<dim3(16, 64), 256, FLASH_SMEM>>>();
    gemm_hmma_kernel<<<dim3(8, 64), 256, GSM_TOTAL>>>(yf, wpf, out, 1);
}

// round 17
// speedup vs baseline: 1.4018x; 1.0098x over previous
#include <cuda_runtime.h>
#include <cuda_fp16.h>
#include <cstdint>
#include <math.h>

// Problem: x[4,2048,1024], W_qkv[3072,1024], W_proj[1024,1024] -> out[4,2048,1024]
#define KDIM 1024

// ---------------- device scratch (allocation-free) ----------------
__device__ __half g_Xf[8388608];
__device__ __half g_Wqf[3145728];
__device__ __half g_Wpf[1048576];
__device__ __half g_Qf[8388608];    // pre-scaled by 0.125*log2(e)  (base-2 logits)
__device__ __half g_Kf[8388608];
__device__ __half g_Vf[8388608];
__device__ __half g_Yf[8388608];

__device__ __forceinline__ uint32_t smem_u32(const void* p) {
    uint32_t a;
    asm("{ .reg .u64 t; cvta.to.shared.u64 t, %1; cvt.u32.u64 %0, t; }" : "=r"(a) : "l"(p));
    return a;
}

#define LDSM_X4(r0, r1, r2, r3, addr) \
    asm volatile("ldmatrix.sync.aligned.m8n8.x4.shared.b16 {%0,%1,%2,%3}, [%4];" \
                 : "=r"(r0), "=r"(r1), "=r"(r2), "=r"(r3) : "r"(addr))

#define LDSM_X4_T(r0, r1, r2, r3, addr) \
    asm volatile("ldmatrix.sync.aligned.m8n8.x4.trans.shared.b16 {%0,%1,%2,%3}, [%4];" \
                 : "=r"(r0), "=r"(r1), "=r"(r2), "=r"(r3) : "r"(addr))

#define MMA16816F(c, a, b) \
    asm volatile("mma.sync.aligned.m16n8k16.row.col.f32.f16.f16.f32 " \
                 "{%0,%1,%2,%3}, {%4,%5,%6,%7}, {%8,%9}, {%0,%1,%2,%3};" \
                 : "+f"((c)[0]), "+f"((c)[1]), "+f"((c)[2]), "+f"((c)[3]) \
                 : "r"((a)[0]), "r"((a)[1]), "r"((a)[2]), "r"((a)[3]), \
                   "r"((b)[0]), "r"((b)[1]))

#define CP_ASYNC16(dst, src) \
    asm volatile("cp.async.cg.shared.global [%0], [%1], 16;" :: "r"(dst), "l"(src) : "memory")
#define CP_COMMIT() asm volatile("cp.async.commit_group;" ::: "memory")
#define CP_WAIT2()  asm volatile("cp.async.wait_group 2;" ::: "memory")
#define CP_WAIT1()  asm volatile("cp.async.wait_group 1;" ::: "memory")
#define CP_WAIT0()  asm volatile("cp.async.wait_group 0;" ::: "memory")

// ---------------------------------------------------------------------------
// merged conv16: fp32 -> fp16 for x, W_qkv, W_proj in ONE launch
// ---------------------------------------------------------------------------
#define N4_X  2097152
#define N4_WQ 786432
#define N4_WP 262144

__global__ __launch_bounds__(256) void conv16_all_kernel(const float* __restrict__ x,
                                                         const float* __restrict__ wq,
                                                         const float* __restrict__ wp)
{
    int i = blockIdx.x * blockDim.x + threadIdx.x;
    const float* src;
    __half* dst;
    int j;
    if (i < N4_X) {
        src = x; dst = g_Xf; j = i;
    } else if (i < N4_X + N4_WQ) {
        src = wq; dst = g_Wqf; j = i - N4_X;
    } else if (i < N4_X + N4_WQ + N4_WP) {
        src = wp; dst = g_Wpf; j = i - N4_X - N4_WQ;
    } else {
        return;
    }
    float4 v = ((const float4*)src)[j];
    __half2 a = __floats2half2_rn(v.x, v.y);
    __half2 b = __floats2half2_rn(v.z, v.w);
    ((uint2*)dst)[j] = make_uint2(*(uint32_t*)&a, *(uint32_t*)&b);
}

// ---------------------------------------------------------------------------
// HMMA fp16 single-pass GEMM: C = A * B^T, fp32 accumulate.
// CTA 128x128, 8 warps (2M x 4N), warp 64x32, K_tile=64, 16 iters.
// 3-stage cp.async ring, ISSUE-BEFORE-WAIT, wait_group 2 -> true depth-2
// prefetch with issue off the critical path (unlike R8's failed variant,
// which issued after the barrier and waited at depth 1). Both barriers kept:
// bottom barrier of iter i-1 fences old reads of the stage iter i re-issues.
// smem 3x36864=110592/CTA; x2 CTAs = 221KB <= 228KB pool. regs 128, 2 CTA/SM.
// mode 0: QKV -> Qf(x 0.125*log2e), Kf, Vf;  mode 1: row-major fp32 Out
// ---------------------------------------------------------------------------
#define GTILE  (128 * 144)           // 18432 B
#define GSTAGE (2 * GTILE)           // 36864 B: A, B
#define GSM_TOTAL (3 * GSTAGE)       // 110592 B

__global__ __launch_bounds__(256, 2)
void gemm_hmma_kernel(const __half* __restrict__ A,
                      const __half* __restrict__ B,
                      float* __restrict__ Out, int mode)
{
    extern __shared__ char smem[];
    const int tid = threadIdx.x;
    const int wid = tid >> 5;
    const int l = tid & 31;
    const int m0 = blockIdx.y << 7;
    const int n0 = blockIdx.x << 7;
    const int warpM = wid >> 2;
    const int warpN = wid & 3;

    float acc[4][4][4];
#pragma unroll
    for (int i = 0; i < 4; ++i)
#pragma unroll
        for (int j = 0; j < 4; ++j)
#pragma unroll
            for (int k = 0; k < 4; ++k) acc[i][j][k] = 0.f;

    const int aRow = warpM * 64 + (l & 15);
    const uint32_t aOff = (uint32_t)(aRow * 144 + (((l >> 4) << 3) << 1));
    const int bRow = warpN * 32 + (l & 7) + ((l >> 4) << 3);
    const uint32_t bOff = (uint32_t)(bRow * 144 + ((((l >> 3) & 1) << 3) << 1));
    const uint32_t smb = smem_u32(smem);

    // stage issue: 2048 16B chunks, 8 per thread
    auto issue = [&](int stg, int k0) {
        char* st = smem + stg * GSTAGE;
#pragma unroll
        for (int t = 0; t < 8; ++t) {
            int ci = tid + (t << 8);         // 0..2047
            int mat = ci >> 10;              // 0 A, 1 B
            int pos = ci & 1023;
            int row = pos >> 3;
            int q = pos & 7;
            const __half* src = mat ? B : A;
            int grow = (mat ? n0 : m0) + row;
            uint32_t dst = smem_u32(st + mat * GTILE + row * 144 + (q << 4));
            CP_ASYNC16(dst, src + (size_t)grow * KDIM + k0 + (q << 3));
        }
        CP_COMMIT();
    };

    issue(0, 0);
    issue(1, 64);
    int cur = 0;                     // iter % 3, maintained incrementally
    for (int iter = 0; iter < 16; ++iter) {
        if (iter + 2 < 16) {
            int nx = cur + 2; if (nx >= 3) nx -= 3;
            issue(nx, (iter + 2) << 6);
            CP_WAIT2();
        } else if (iter == 14) {
            CP_WAIT1();
        } else {
            CP_WAIT0();
        }
        __syncthreads();

        const uint32_t sb = smb + (uint32_t)(cur * GSTAGE);
        const uint32_t sA_u = sb + aOff;
        const uint32_t sB_u = sb + GTILE + bOff;

#pragma unroll
        for (int ks = 0; ks < 4; ++ks) {
            const uint32_t kb = (uint32_t)(ks << 5);
            uint32_t bf[4][2];
#pragma unroll
            for (int np = 0; np < 2; ++np) {
                uint32_t o = kb + (uint32_t)(np * 16 * 144);
                LDSM_X4(bf[2 * np][0], bf[2 * np][1], bf[2 * np + 1][0], bf[2 * np + 1][1], sB_u + o);
            }
            uint32_t af[4][4];
#pragma unroll
            for (int mt = 0; mt < 4; ++mt) {
                uint32_t o = kb + (uint32_t)(mt * 16 * 144);
                LDSM_X4(af[mt][0], af[mt][1], af[mt][2], af[mt][3], sA_u + o);
            }
#pragma unroll
            for (int mt = 0; mt < 4; ++mt)
#pragma unroll
                for (int nt = 0; nt < 4; ++nt)
                    MMA16816F(acc[mt][nt], af[mt], bf[nt]);
        }
        __syncthreads();

        if (++cur >= 3) cur = 0;
    }

    // epilogue
#pragma unroll
    for (int mt = 0; mt < 4; ++mt) {
#pragma unroll
        for (int nt = 0; nt < 4; ++nt) {
            int r0 = m0 + warpM * 64 + mt * 16 + (l >> 2);
            int col = n0 + warpN * 32 + nt * 8 + ((l & 3) << 1);
#pragma unroll
            for (int half = 0; half < 2; ++half) {
                int m = r0 + half * 8;
                float vx = acc[mt][nt][half * 2], vy = acc[mt][nt][half * 2 + 1];
                if (mode == 0) {
                    int which = col >> 10;
                    int c = col & 1023;
                    int h = c >> 6;
                    int d = c & 63;
                    int bb = m >> 11;
                    int t = m & 2047;
                    size_t idx = (size_t)(((bb << 4) | h) * 2048 + t) * 64 + d;
                    if (which == 0) {
                        // 0.125 * log2(e): base-2 logits for h2exp2 softmax
                        const float QS = 0.18033688f;
                        *(__half2*)&g_Qf[idx] = __floats2half2_rn(vx * QS, vy * QS);
                    } else if (which == 1) {
                        *(__half2*)&g_Kf[idx] = __floats2half2_rn(vx, vy);
                    } else {
                        *(__half2*)&g_Vf[idx] = __floats2half2_rn(vx, vy);
                    }
                } else {
                    *(float2*)&Out[(size_t)m * 1024 + col] = make_float2(vx, vy);
                }
            }
        }
    }
}

// ---------------------------------------------------------------------------
// Flash attention, fp16 HMMA, base-2 h2exp2 softmax. (R14 structure — best)
// 4-stage KV ring, TWO tiles processed per wait+barrier.
// smem: Qf [0,18432); stage s at 18432 + s*18432 (s=0..3): K[0,9216) V[9216,)
// ---------------------------------------------------------------------------
#define FQ_SZ 18432
#define FSTAGE 18432
#define FLASH_SMEM (FQ_SZ + 4 * FSTAGE)   // 92160 (x2 CTAs = 184320 fits)

__device__ __forceinline__ void kv_issue(int tid, char* sb, int k0,
                                         const __half* Kf, const __half* Vf)
{
#pragma unroll
    for (int t = 0; t < 4; ++t) {
        int ci = tid + (t << 8);          // 0..1023
        int mat = ci >> 9;                // 0 K, 1 V
        int r = (ci & 511) >> 3;
        int q = ci & 7;
        const __half* src = mat ? Vf : Kf;
        uint32_t dst = smem_u32(sb + mat * 9216 + r * 144 + (q << 4));
        CP_ASYNC16(dst, src + (size_t)(k0 + r) * 64 + (q << 3));
    }
    CP_COMMIT();
}

__global__ __launch_bounds__(256, 2) void flash_hmma_kernel()
{
    extern __shared__ char sm[];
    const int tid = threadIdx.x;
    const int w = tid >> 5;
    const int l = tid & 31;
    const int bh = blockIdx.y;
    const int q0 = blockIdx.x << 7;

    const size_t hb = (size_t)bh * 2048 * 64;
    const __half* Qp = g_Qf + hb;
    const __half* Kp = g_Kf + hb;
    const __half* Vp = g_Vf + hb;

    // Q tile -> smem
#pragma unroll
    for (int t = 0; t < 4; ++t) {
        int ci = tid + (t << 8);
        int r = ci >> 3;
        int q = ci & 7;
        *(uint4*)(sm + r * 144 + (q << 4)) = *(const uint4*)(Qp + (size_t)(q0 + r) * 64 + (q << 3));
    }
    // prologue: tiles 0 and 1 into slots 0,1
    kv_issue(tid, sm + FQ_SZ + 0 * FSTAGE, 0, Kp, Vp);
    kv_issue(tid, sm + FQ_SZ + 1 * FSTAGE, 64, Kp, Vp);
    __syncthreads();    // Q stores visible for LDSM below

    uint32_t qf[4][4];
    {
        uint32_t qb = smem_u32(sm) + (uint32_t)((w * 16 + (l & 15)) * 144 + (((l >> 4) << 3) << 1));
#pragma unroll
        for (int ks = 0; ks < 4; ++ks)
            LDSM_X4(qf[ks][0], qf[ks][1], qf[ks][2], qf[ks][3], qb + ks * 32);
    }

    float o[8][4];
#pragma unroll
    for (int nt = 0; nt < 8; ++nt)
#pragma unroll
        for (int j = 0; j < 4; ++j) o[nt][j] = 0.f;
    float m_[2] = {-INFINITY, -INFINITY};
    float l_[2] = {0.f, 0.f};

    const uint32_t kb_off = (uint32_t)((((l & 7) + ((l >> 4) << 3)) * 144) + ((((l >> 3) & 1) << 3) << 1));
    const uint32_t vb_off = (uint32_t)((((l & 7) + (((l >> 3) & 1) << 3)) * 144) + (((l >> 4) << 3) << 1));

    for (int i2 = 0; i2 < 16; ++i2) {
        CP_WAIT0();          // tiles 2*i2, 2*i2+1 landed
        __syncthreads();     // cross-thread visibility + fences prior reads of reused slots
        if (i2 < 15) {
            kv_issue(tid, sm + FQ_SZ + ((2 * i2 + 2) & 3) * FSTAGE, (2 * i2 + 2) << 6, Kp, Vp);
            kv_issue(tid, sm + FQ_SZ + ((2 * i2 + 3) & 3) * FSTAGE, (2 * i2 + 3) << 6, Kp, Vp);
        }

#pragma unroll
        for (int half = 0; half < 2; ++half) {
            const int jb = 2 * i2 + half;
            char* sb = sm + FQ_SZ + (jb & 3) * FSTAGE;
            const uint32_t kbase = smem_u32(sb) + kb_off;
            const uint32_t vbase = smem_u32(sb) + 9216 + vb_off;

            // S = Q K^T (base-2 logits; Q pre-scaled by 0.125*log2e)
            float s[8][4];
#pragma unroll
            for (int nt = 0; nt < 8; ++nt)
#pragma unroll
                for (int j = 0; j < 4; ++j) s[nt][j] = 0.f;

#pragma unroll
            for (int ks = 0; ks < 4; ++ks) {
                uint32_t kh_[8][2];
#pragma unroll
                for (int np = 0; np < 4; ++np) {
                    uint32_t off = (uint32_t)(np * 16 * 144) + ks * 32;
                    LDSM_X4(kh_[2 * np][0], kh_[2 * np][1], kh_[2 * np + 1][0], kh_[2 * np + 1][1], kbase + off);
                }
#pragma unroll
                for (int nt = 0; nt < 8; ++nt)
                    MMA16816F(s[nt], qf[ks], kh_[nt]);
            }

            // online softmax, base-2
            float mx[2] = {-INFINITY, -INFINITY};
#pragma unroll
            for (int nt = 0; nt < 8; ++nt) {
                mx[0] = fmaxf(mx[0], fmaxf(s[nt][0], s[nt][1]));
                mx[1] = fmaxf(mx[1], fmaxf(s[nt][2], s[nt][3]));
            }
#pragma unroll
            for (int r = 0; r < 2; ++r) {
                mx[r] = fmaxf(mx[r], __shfl_xor_sync(0xffffffffu, mx[r], 1));
                mx[r] = fmaxf(mx[r], __shfl_xor_sync(0xffffffffu, mx[r], 2));
            }
            float mn[2], al[2];
#pragma unroll
            for (int r = 0; r < 2; ++r) {
                mn[r] = fmaxf(m_[r], mx[r]);
                al[r] = exp2f(m_[r] - mn[r]);
                m_[r] = mn[r];
            }

            // P = 2^(s - mn) as fp16 pairs (these ARE the PV A-fragments)
            uint32_t ph[8][2];
            float rs0 = 0.f, rs1 = 0.f;
#pragma unroll
            for (int nt = 0; nt < 8; ++nt) {
                __half2 e0 = h2exp2(__floats2half2_rn(s[nt][0] - mn[0], s[nt][1] - mn[0]));
                __half2 e1 = h2exp2(__floats2half2_rn(s[nt][2] - mn[1], s[nt][3] - mn[1]));
                ph[nt][0] = *(uint32_t*)&e0;
                ph[nt][1] = *(uint32_t*)&e1;
                float2 f0 = __half22float2(e0);
                float2 f1 = __half22float2(e1);
                rs0 += f0.x + f0.y;
                rs1 += f1.x + f1.y;
            }
            float rs[2] = {rs0, rs1};
#pragma unroll
            for (int r = 0; r < 2; ++r) {
                rs[r] += __shfl_xor_sync(0xffffffffu, rs[r], 1);
                rs[r] += __shfl_xor_sync(0xffffffffu, rs[r], 2);
                l_[r] = l_[r] * al[r] + rs[r];
            }
#pragma unroll
            for (int nt = 0; nt < 8; ++nt) {
                o[nt][0] *= al[0]; o[nt][1] *= al[0];
                o[nt][2] *= al[1]; o[nt][3] *= al[1];
            }

            // O += P V
#pragma unroll
            for (int ks = 0; ks < 4; ++ks) {
                const int ta = 2 * ks, tb = 2 * ks + 1;
                uint32_t pa[4] = {ph[ta][0], ph[ta][1], ph[tb][0], ph[tb][1]};
                uint32_t vf_[8][2];
#pragma unroll
                for (int np = 0; np < 4; ++np) {
                    uint32_t off = (uint32_t)(ks * 16 * 144) + np * 32;
                    LDSM_X4_T(vf_[2 * np][0], vf_[2 * np][1], vf_[2 * np + 1][0], vf_[2 * np + 1][1], vbase + off);
                }
#pragma unroll
                for (int nt = 0; nt < 8; ++nt)
                    MMA16816F(o[nt], pa, vf_[nt]);
            }
        }
    }

    // epilogue: Y = O / l, fp16, layout [B,T,C]
    const int bb = bh >> 4;
    const int hh = bh & 15;
#pragma unroll
    for (int r = 0; r < 2; ++r) {
        int t = q0 + w * 16 + (l >> 2) + r * 8;
        float inv = 1.f / l_[r];
        size_t rowbase = (size_t)(bb * 2048 + t) * 1024 + hh * 64 + ((l & 3) << 1);
#pragma unroll
        for (int nt = 0; nt < 8; ++nt) {
            __half2 y2 = __floats2half2_rn(o[nt][2 * r] * inv, o[nt][2 * r + 1] * inv);
            *(__half2*)&g_Yf[rowbase + nt * 8] = y2;
        }
    }
}

// ---------------------------------------------------------------------------
extern "C" void kernel_launch(void* const* d_in, const int* in_sizes, int n_in,
                              void* d_out, int out_size)
{
    (void)in_sizes; (void)n_in; (void)out_size;
    const float* x = (const float*)d_in[0];
    const float* wq = (const float*)d_in[1];
    const float* wp = (const float*)d_in[2];
    float* out = (float*)d_out;

    cudaFuncSetAttribute(gemm_hmma_kernel, cudaFuncAttributeMaxDynamicSharedMemorySize, GSM_TOTAL);
    cudaFuncSetAttribute(flash_hmma_kernel, cudaFuncAttributeMaxDynamicSharedMemorySize, FLASH_SMEM);

    __half *xf, *wqf, *wpf, *yf;
    cudaGetSymbolAddress((void**)&xf, g_Xf);
    cudaGetSymbolAddress((void**)&wqf, g_Wqf);
    cudaGetSymbolAddress((void**)&wpf, g_Wpf);
    cudaGetSymbolAddress((void**)&yf, g_Yf);

    conv16_all_kernel<<<12288, 256>>>(x, wq, wp);

    gemm_hmma_kernel<<<dim3(24, 64), 256, GSM_TOTAL>>>(xf, wqf, nullptr, 0);
    flash_hmma_kernel<<<dim3(16, 64), 256, FLASH_SMEM>>>();
    gemm_hmma_kernel<<<dim3(8, 64), 256, GSM_TOTAL>>>(yf, wpf, out, 1);
}